// round 16
// baseline (speedup 1.0000x reference)
#include <cuda_runtime.h>
#include <cstdint>

// Problem constants (fixed: midis_out is (16, 11, 65536) fp32, LST=64)
#define NB      16
#define NI      11
#define NT      65536
#define LSTLEN  64
#define NBLK    (NB * NI * (NT / LSTLEN))   // 180224 time-blocks total
#define THREADS 256
#define CHUNK   512                          // columns per CTA in kernel 2
#define NCHUNK  (NT / CHUNK)                 // 128

// Scratch for per-64-block taus (allocation-free: device global)
__device__ float g_tau_time[NBLK];

// ============================ Kernel 1 =====================================
// Exact sparsemax tau over one 64-block held as 8 elems/lane across an
// 8-lane segment. Michelot from safe warm start tau0 = max-1 (tau* >= max-1
// since max output <= 1): 2 unconditional iterations + convergence-checked
// guard loop (the check IS a full pass -> exact).
__device__ __forceinline__ float tau64_seg(const float z[8]) {
    float m = fmaxf(fmaxf(fmaxf(z[0], z[1]), fmaxf(z[2], z[3])),
                    fmaxf(fmaxf(z[4], z[5]), fmaxf(z[6], z[7])));
    #pragma unroll
    for (int o = 4; o; o >>= 1)
        m = fmaxf(m, __shfl_xor_sync(0xFFFFFFFFu, m, o));

    float tau = m - 1.0f;
    float cf  = 0.0f;

    #pragma unroll
    for (int it = 0; it < 2; ++it) {
        float ss = 0.0f; cf = 0.0f;
        #pragma unroll
        for (int j = 0; j < 8; ++j)
            if (z[j] > tau) { ss += z[j]; cf += 1.0f; }
        #pragma unroll
        for (int o = 4; o; o >>= 1) {
            ss += __shfl_xor_sync(0xFFFFFFFFu, ss, o);
            cf += __shfl_xor_sync(0xFFFFFFFFu, cf, o);
        }
        tau = __fdividef(ss - 1.0f, cf);
    }

    int k = (int)cf;
    #pragma unroll 1
    for (;;) {
        float ss = 0.0f, c2 = 0.0f;
        #pragma unroll
        for (int j = 0; j < 8; ++j)
            if (z[j] > tau) { ss += z[j]; c2 += 1.0f; }
        #pragma unroll
        for (int o = 4; o; o >>= 1) {
            ss += __shfl_xor_sync(0xFFFFFFFFu, ss, o);
            c2 += __shfl_xor_sync(0xFFFFFFFFu, c2, o);
        }
        const int kn = (int)c2;
        const bool conv = (kn >= k);
        if (__all_sync(0xFFFFFFFFu, conv)) break;
        if (!conv) { tau = __fdividef(ss - 1.0f, c2); k = kn; }
    }
    return tau;
}

// One warp = 8 blocks (two per 8-lane segment); ALL loads issued up front
// for MLP=4 per thread, then both reductions. Triggers the dependent
// launch of kernel 2 as soon as its loads are issued (PDL overlap).
__global__ __launch_bounds__(THREADS)
void tau_time_kernel(const float* __restrict__ in)
{
    const int lane = threadIdx.x & 31;
    const int gwarp = (blockIdx.x * (THREADS / 32)) + (threadIdx.x >> 5);
    const int seg = lane >> 3;
    const int sl  = lane & 7;

    const int blkA = gwarp * 8 + seg;        // NBLK divisible by 8
    const int blkB = blkA + 4;

    const float* pA = in + (size_t)blkA * LSTLEN + sl * 8;
    const float* pB = in + (size_t)blkB * LSTLEN + sl * 8;
    const float4 a0 = *(const float4*)pA;
    const float4 a1 = *(const float4*)(pA + 4);
    const float4 b0 = *(const float4*)pB;
    const float4 b1 = *(const float4*)(pB + 4);

    // Let kernel 2 start launching: its pre-sync work (loads + sorts) is
    // independent of our tau stores; it gridDependencySync's before reading.
    cudaTriggerProgrammaticLaunchCompletion();

    const float zA[8] = {a0.x, a0.y, a0.z, a0.w, a1.x, a1.y, a1.z, a1.w};
    const float zB[8] = {b0.x, b0.y, b0.z, b0.w, b1.x, b1.y, b1.z, b1.w};

    const float tauA = tau64_seg(zA);
    const float tauB = tau64_seg(zB);
    if (sl == 0) {
        g_tau_time[blkA] = tauA;
        g_tau_time[blkB] = tauB;
    }
}

// ============================ Kernel 2 =====================================

__device__ __forceinline__ void ce(float& a, float& b) {
    const float lo = fminf(a, b), hi = fmaxf(a, b);
    a = lo; b = hi;
}

// Optimal 11-input sorting network (35 CE, depth 8), ascending.
__device__ __forceinline__ void sort11(float z[NI]) {
    ce(z[0],z[9]); ce(z[1],z[6]); ce(z[2],z[4]); ce(z[3],z[7]); ce(z[5],z[8]);
    ce(z[0],z[1]); ce(z[3],z[5]); ce(z[4],z[10]); ce(z[6],z[9]); ce(z[7],z[8]);
    ce(z[1],z[3]); ce(z[2],z[5]); ce(z[4],z[7]); ce(z[8],z[10]);
    ce(z[0],z[4]); ce(z[1],z[2]); ce(z[3],z[7]); ce(z[5],z[9]); ce(z[6],z[8]);
    ce(z[0],z[1]); ce(z[2],z[6]); ce(z[4],z[5]); ce(z[7],z[8]); ce(z[9],z[10]);
    ce(z[2],z[4]); ce(z[3],z[6]); ce(z[5],z[7]); ce(z[8],z[9]);
    ce(z[1],z[2]); ce(z[3],z[4]); ce(z[5],z[6]); ce(z[7],z[8]);
    ce(z[2],z[3]); ce(z[4],z[5]); ce(z[6],z[7]);
}

// Exact sparsemax tau over 11 values (destroys z).
// tau* = max_{k=1..d} (csum_k - 1)/k over the DESCENDING cumsum.
__device__ __forceinline__ float sparsemax11_tau(float z[NI]) {
    sort11(z);
    float cs  = z[NI - 1];
    float tau = cs - 1.0f;
    #pragma unroll
    for (int k = 2; k <= NI; ++k) {
        cs += z[NI - k];
        const float rk = 1.0f / (float)k;          // compile-time constant
        tau = fmaxf(tau, fmaf(cs, rk, -rk));       // (cs-1)/k
    }
    return tau;
}

// Per-column instrument sparsemax + multiply, no SMEM, no barriers.
// Launched with programmatic stream serialization: overlaps its load+sort
// front half with tau_time_kernel's tail, then gridDependencySync's before
// touching g_tau_time. Output stores are evict-first (__stcs) to preserve
// the input's L2 residency across graph replays.
__global__ __launch_bounds__(THREADS)
void sparsemax_mul_kernel(const float* __restrict__ in,
                          float* __restrict__ out)
{
    const int tid = threadIdx.x;
    const int b = blockIdx.x / NCHUNK;
    const int c = blockIdx.x % NCHUNK;
    const int t0 = tid * 2;
    const unsigned base = (unsigned)(b * NI) * NT + (unsigned)(c * CHUNK) + (unsigned)t0;

    // Independent front half: data loads (MLP=11) + both column sparsemaxes
    float2 v[NI];
    #pragma unroll
    for (int i = 0; i < NI; ++i)
        v[i] = *(const float2*)(in + base + (unsigned)(i * NT));

    float za[NI], zb[NI];
    #pragma unroll
    for (int i = 0; i < NI; ++i) { za[i] = v[i].x; zb[i] = v[i].y; }
    const float ta = sparsemax11_tau(za);
    const float tb = sparsemax11_tau(zb);

    // Wait for tau_time_kernel's grid (memory now visible)
    cudaGridDependencySynchronize();

    // warp-uniform 64-block index within this (b, chunk)
    const int blkb = (b * NI) * (NT / LSTLEN) + c * (CHUNK / LSTLEN) + (t0 >> 6);
    #pragma unroll
    for (int i = 0; i < NI; ++i) {
        const float tt = g_tau_time[blkb + i * (NT / LSTLEN)];
        float2 r;
        r.x = fmaxf(v[i].x - ta, 0.0f) * fmaxf(v[i].x - tt, 0.0f);
        r.y = fmaxf(v[i].y - tb, 0.0f) * fmaxf(v[i].y - tt, 0.0f);
        __stcs((float2*)(out + base + (unsigned)(i * NT)), r);
    }
}

extern "C" void kernel_launch(void* const* d_in, const int* in_sizes, int n_in,
                              void* d_out, int out_size)
{
    const float* in = (const float*)d_in[0];
    float* out = (float*)d_out;

    // Kernel 1: 8 blocks per warp, 8 warps per CTA -> 64 blocks per CTA
    tau_time_kernel<<<NBLK / 64, THREADS>>>(in);

    // Kernel 2: PDL secondary — may begin launching once kernel 1's CTAs
    // have triggered; synchronizes internally before reading g_tau_time.
    cudaLaunchConfig_t cfg = {};
    cfg.gridDim  = dim3(NB * NCHUNK, 1, 1);
    cfg.blockDim = dim3(THREADS, 1, 1);
    cudaLaunchAttribute attrs[1];
    attrs[0].id = cudaLaunchAttributeProgrammaticStreamSerialization;
    attrs[0].val.programmaticStreamSerializationAllowed = 1;
    cfg.attrs = attrs;
    cfg.numAttrs = 1;
    cudaLaunchKernelEx(&cfg, sparsemax_mul_kernel, in, out);
}

// round 17
// speedup vs baseline: 1.1669x; 1.1669x over previous
#include <cuda_runtime.h>
#include <cstdint>

// Problem constants (fixed: midis_out is (16, 11, 65536) fp32, LST=64)
#define NB      16
#define NI      11
#define NT      65536
#define LSTLEN  64
#define NBLK    (NB * NI * (NT / LSTLEN))   // 180224 time-blocks total
#define THREADS 256
#define CHUNK   1024                         // columns per CTA in kernel 2
#define NCHUNK  (NT / CHUNK)                 // 64

// Scratch for per-64-block taus (allocation-free: device global)
__device__ float g_tau_time[NBLK];

// ============================ Kernel 1 (R15, measured ~10.1us) =============
// Exact sparsemax tau over one 64-block held as 8 elems/lane across an
// 8-lane segment. Michelot from safe warm start tau0 = max-1 (tau* >= max-1
// since max output <= 1): 2 unconditional iterations + convergence-checked
// guard loop (the check IS a full pass -> exact).
__device__ __forceinline__ float tau64_seg(const float z[8]) {
    float m = fmaxf(fmaxf(fmaxf(z[0], z[1]), fmaxf(z[2], z[3])),
                    fmaxf(fmaxf(z[4], z[5]), fmaxf(z[6], z[7])));
    #pragma unroll
    for (int o = 4; o; o >>= 1)
        m = fmaxf(m, __shfl_xor_sync(0xFFFFFFFFu, m, o));

    float tau = m - 1.0f;
    float cf  = 0.0f;

    #pragma unroll
    for (int it = 0; it < 2; ++it) {
        float ss = 0.0f; cf = 0.0f;
        #pragma unroll
        for (int j = 0; j < 8; ++j)
            if (z[j] > tau) { ss += z[j]; cf += 1.0f; }
        #pragma unroll
        for (int o = 4; o; o >>= 1) {
            ss += __shfl_xor_sync(0xFFFFFFFFu, ss, o);
            cf += __shfl_xor_sync(0xFFFFFFFFu, cf, o);
        }
        tau = __fdividef(ss - 1.0f, cf);
    }

    int k = (int)cf;
    #pragma unroll 1
    for (;;) {
        float ss = 0.0f, c2 = 0.0f;
        #pragma unroll
        for (int j = 0; j < 8; ++j)
            if (z[j] > tau) { ss += z[j]; c2 += 1.0f; }
        #pragma unroll
        for (int o = 4; o; o >>= 1) {
            ss += __shfl_xor_sync(0xFFFFFFFFu, ss, o);
            c2 += __shfl_xor_sync(0xFFFFFFFFu, c2, o);
        }
        const int kn = (int)c2;
        const bool conv = (kn >= k);
        if (__all_sync(0xFFFFFFFFu, conv)) break;
        if (!conv) { tau = __fdividef(ss - 1.0f, c2); k = kn; }
    }
    return tau;
}

// One warp = 8 blocks (two per 8-lane segment); ALL loads issued up front
// for MLP=4 per thread, then both reductions.
__global__ __launch_bounds__(THREADS)
void tau_time_kernel(const float* __restrict__ in)
{
    const int lane = threadIdx.x & 31;
    const int gwarp = (blockIdx.x * (THREADS / 32)) + (threadIdx.x >> 5);
    const int seg = lane >> 3;
    const int sl  = lane & 7;

    const int blkA = gwarp * 8 + seg;        // NBLK divisible by 8
    const int blkB = blkA + 4;

    const float* pA = in + (size_t)blkA * LSTLEN + sl * 8;
    const float* pB = in + (size_t)blkB * LSTLEN + sl * 8;
    const float4 a0 = *(const float4*)pA;
    const float4 a1 = *(const float4*)(pA + 4);
    const float4 b0 = *(const float4*)pB;
    const float4 b1 = *(const float4*)(pB + 4);

    const float zA[8] = {a0.x, a0.y, a0.z, a0.w, a1.x, a1.y, a1.z, a1.w};
    const float zB[8] = {b0.x, b0.y, b0.z, b0.w, b1.x, b1.y, b1.z, b1.w};

    const float tauA = tau64_seg(zA);
    const float tauB = tau64_seg(zB);
    if (sl == 0) {
        g_tau_time[blkA] = tauA;
        g_tau_time[blkB] = tauB;
    }
}

// ============================ Kernel 2 =====================================

__device__ __forceinline__ void ce(float& a, float& b) {
    const float lo = fminf(a, b), hi = fmaxf(a, b);
    a = lo; b = hi;
}

// Optimal 11-input sorting network (35 CE, depth 8), ascending.
__device__ __forceinline__ void sort11(float z[NI]) {
    ce(z[0],z[9]); ce(z[1],z[6]); ce(z[2],z[4]); ce(z[3],z[7]); ce(z[5],z[8]);
    ce(z[0],z[1]); ce(z[3],z[5]); ce(z[4],z[10]); ce(z[6],z[9]); ce(z[7],z[8]);
    ce(z[1],z[3]); ce(z[2],z[5]); ce(z[4],z[7]); ce(z[8],z[10]);
    ce(z[0],z[4]); ce(z[1],z[2]); ce(z[3],z[7]); ce(z[5],z[9]); ce(z[6],z[8]);
    ce(z[0],z[1]); ce(z[2],z[6]); ce(z[4],z[5]); ce(z[7],z[8]); ce(z[9],z[10]);
    ce(z[2],z[4]); ce(z[3],z[6]); ce(z[5],z[7]); ce(z[8],z[9]);
    ce(z[1],z[2]); ce(z[3],z[4]); ce(z[5],z[6]); ce(z[7],z[8]);
    ce(z[2],z[3]); ce(z[4],z[5]); ce(z[6],z[7]);
}

// Exact sparsemax tau over 11 values (destroys z).
// tau* = max_{k=1..d} (csum_k - 1)/k over the DESCENDING cumsum.
__device__ __forceinline__ float sparsemax11_tau(float z[NI]) {
    sort11(z);
    float cs  = z[NI - 1];
    float tau = cs - 1.0f;
    #pragma unroll
    for (int k = 2; k <= NI; ++k) {
        cs += z[NI - k];
        const float rk = 1.0f / (float)k;          // compile-time constant
        tau = fmaxf(tau, fmaf(cs, rk, -rk));       // (cs-1)/k
    }
    return tau;
}

// 4 adjacent columns per thread with float4 LDG/STG.128: half the memory
// instructions per byte vs the float2 version. No SMEM, no barriers.
// Output stores are evict-first (__stcs): the output is never re-read, so
// keeping it OUT of L2 preserves the input's residency for the next
// replay's tau_time_kernel pass.
__global__ __launch_bounds__(THREADS)
void sparsemax_mul_kernel(const float* __restrict__ in,
                          float* __restrict__ out)
{
    const int tid = threadIdx.x;
    const int b = blockIdx.x / NCHUNK;
    const int c = blockIdx.x % NCHUNK;
    const int t0 = tid * 4;
    const unsigned base = (unsigned)(b * NI) * NT + (unsigned)(c * CHUNK) + (unsigned)t0;

    // Issue all data loads first (MLP=11, LDG.128)
    float4 v[NI];
    #pragma unroll
    for (int i = 0; i < NI; ++i)
        v[i] = *(const float4*)(in + base + (unsigned)(i * NT));

    // Issue tau_time loads early (half-warp-uniform, L2-hot, consumed late)
    const int blkb = (b * NI) * (NT / LSTLEN) + c * (CHUNK / LSTLEN) + (t0 >> 6);
    float tt[NI];
    #pragma unroll
    for (int i = 0; i < NI; ++i)
        tt[i] = g_tau_time[blkb + i * (NT / LSTLEN)];

    // Instrument sparsemax per column: two sequential pairs, reusing scratch
    float ta0, ta1, ta2, ta3;
    {
        float za[NI], zb[NI];
        #pragma unroll
        for (int i = 0; i < NI; ++i) { za[i] = v[i].x; zb[i] = v[i].y; }
        ta0 = sparsemax11_tau(za);
        ta1 = sparsemax11_tau(zb);
        #pragma unroll
        for (int i = 0; i < NI; ++i) { za[i] = v[i].z; zb[i] = v[i].w; }
        ta2 = sparsemax11_tau(za);
        ta3 = sparsemax11_tau(zb);
    }

    #pragma unroll
    for (int i = 0; i < NI; ++i) {
        float4 r;
        r.x = fmaxf(v[i].x - ta0, 0.0f) * fmaxf(v[i].x - tt[i], 0.0f);
        r.y = fmaxf(v[i].y - ta1, 0.0f) * fmaxf(v[i].y - tt[i], 0.0f);
        r.z = fmaxf(v[i].z - ta2, 0.0f) * fmaxf(v[i].z - tt[i], 0.0f);
        r.w = fmaxf(v[i].w - ta3, 0.0f) * fmaxf(v[i].w - tt[i], 0.0f);
        __stcs((float4*)(out + base + (unsigned)(i * NT)), r);
    }
}

extern "C" void kernel_launch(void* const* d_in, const int* in_sizes, int n_in,
                              void* d_out, int out_size)
{
    const float* in = (const float*)d_in[0];
    float* out = (float*)d_out;
    // Kernel 1: 8 blocks per warp, 8 warps per CTA -> 64 blocks per CTA
    tau_time_kernel<<<NBLK / 64, THREADS>>>(in);
    // Kernel 2: 1024 CTAs x 256 threads, 4 columns per thread
    sparsemax_mul_kernel<<<NB * NCHUNK * (CHUNK / 1024), THREADS>>>(in, out);
}